// round 15
// baseline (speedup 1.0000x reference)
#include <cuda_runtime.h>
#include <cuda_bf16.h>
#include <math.h>
#include <string.h>

// ============================================================================
// Problem constants
// ============================================================================
#define NN    20000
#define NGR   5000
#define EMAX  320000
#define GR    52             // padded per-(node,zs) G row (51 used + 1 pad)
#define QR    72             // padded per-(node,zd) Q row
#define CSTR  992            // 62 slots x 16 padded coeffs per (zn,zd) combo
#define PTB   79             // ceil(NN/256) blocks for node-table build

// ============================================================================
// Device scratch (static — no allocation allowed).
// INVARIANT: g_G4, g_NS4, g_out8 are zero at kernel_launch entry (zero-init at
// load; k_q re-zeroes G/NS after consuming, k_final re-zeroes out8).
// ============================================================================
__device__ float4 g_G4[(size_t)NN * 4 * GR / 4];     // 16.6 MB G accumulators
__device__ float4 g_NS4[(size_t)NN * 12 / 4];        // padded node_sh (9 used)
__device__ float4 g_Q4[(size_t)NN * 4 * QR / 4];     // 23 MB Q tables
// fused W1*W2 operator, WORD-MAJOR: [combo][g-word][slot] of float4
// index of float4: (combo*4 + g)*62 + slot
__device__ __align__(16) float g_C[16 * CSTR];
__device__ float4 g_out8[(size_t)NGR * 2];           // padded output accumulator
__device__ float4 g_ER[EMAX];                        // per-edge record: ev + meta
__device__ float4 g_PT[NN];                          // packed node table: pos + (z|batch<<2)
__device__ unsigned int g_tab[62];                   // per-slot: 4x6b G-offsets + 6b pos

// ============================================================================
// Parameter structs
// ============================================================================
struct TP1P {
    float c000;
    float d011[3], d022[5], d101[3], d110[3], d202[5], d220[5];
    float c111[27], c112[45], c121[45], c122[75];
    float c211[45], c212[75], c221[75], c222[125];
};
struct TP2P  { float d110[3]; float d220[5]; };
struct PREPP { float s1[5]; float s20, s21, q0s; };

// ============================================================================
// Helpers
// ============================================================================
__device__ __forceinline__ void compute_sh(float x, float y, float z, float sh[9]) {
    const float s3  = 1.7320508075688772f;
    const float s15 = 3.8729833462074170f;
    const float s5  = 2.2360679774997896f;
    float r2 = x * x + y * y + z * z;
    sh[0] = 1.0f;
    sh[1] = s3 * y; sh[2] = s3 * z; sh[3] = s3 * x;
    sh[4] = s15 * x * y;
    sh[5] = s15 * y * z;
    sh[6] = 0.5f * s5 * (3.0f * z * z - r2);
    sh[7] = s15 * x * z;
    sh[8] = 0.5f * s15 * (x * x - y * y);
}

__device__ __forceinline__ void red4(float* p, float a, float b, float c, float d) {
    asm volatile("red.global.add.v4.f32 [%0], {%1,%2,%3,%4};"
                 :: "l"(p), "f"(a), "f"(b), "f"(c), "f"(d) : "memory");
}

// ============================================================================
// K0 (fused): node table (blocks 0..78) + operator prep (79..142) + slot table (143)
// ============================================================================
__global__ void k_pt(const float* __restrict__ pos, const int* __restrict__ zarr,
                     const int* __restrict__ batch,
                     const float* __restrict__ w1, const float* __restrict__ w2,
                     PREPP M) {
    int b = blockIdx.x;
    if (b < PTB) {
        int n = b * 256 + threadIdx.x;
        if (n < NN) {
            float4 v;
            v.x = __ldg(pos + 3 * n + 0);
            v.y = __ldg(pos + 3 * n + 1);
            v.z = __ldg(pos + 3 * n + 2);
            v.w = __int_as_float(__ldg(zarr + n) | (__ldg(batch + n) << 2));
            g_PT[n] = v;
        }
        return;
    }
    if (b < PTB + 64) {
        // ---- operator prep (64 blocks: 16 combos x 4 slices of 992 coeffs) ----
        int r = b - PTB;
        int combo = r >> 2, slice = r & 3;
        int zn = combo >> 2, zd = combo & 3;
        int t2 = 4 * zn + zd;
        int f = slice * 256 + threadIdx.x;
        if (f >= CSTR) return;
        int slot = f >> 4, q = f & 15;
        int g = q >> 2, p = q & 3;
        int t1 = 4 * g + zn;
        float v = 0.f;
        if (slot < 6) {                                 // Q0: 3 live paths
            if (p < 3) {
                int off = (p == 0) ? 0 : (p == 1 ? 2048 : 5248);
                float a = 0.f;
                for (int u = 0; u < 64; u++)
                    a += __ldg(w1 + off + t1 * 64 + u) * __ldg(w2 + u * 96 + t2 * 6 + slot);
                v = M.q0s * M.s1[0] * a;
            }
        } else if (slot < 9) {                          // A1: 2 live paths
            if (p < 2) {
                int off = p ? 6272 : 3072;
                float a = 0.f;
                for (int u = 0; u < 24; u++)
                    a += __ldg(w1 + off + t1 * 24 + u) * __ldg(w2 + 6144 + u * 16 + t2);
                v = M.s20 * M.s1[1] * a;
            }
        } else if (slot < 27) {                         // B1: 4 live paths
            int w = (slot - 9) % 6;
            const int offs[4] = {1024, 1664, 3712, 4608};
            float a = 0.f;
            for (int u = 0; u < 24; u++)
                a += __ldg(w1 + offs[p] + t1 * 24 + u) * __ldg(w2 + 6528 + u * 96 + t2 * 6 + w);
            v = M.s21 * M.s1[2] * a;
        } else if (slot < 32) {                         // A2: 2 live paths
            if (p < 2) {
                int off = p ? 4992 : 4096;
                float a = 0.f;
                for (int u = 0; u < 16; u++)
                    a += __ldg(w1 + off + t1 * 16 + u) * __ldg(w2 + 10368 + u * 16 + t2);
                v = M.s20 * M.s1[4] * a;
            }
        } else {                                        // B2: 4 live paths
            int w = (slot - 32) % 6;
            const int offs[4] = {1408, 3456, 4352, 6656};
            float a = 0.f;
            for (int u = 0; u < 16; u++)
                a += __ldg(w1 + offs[p] + t1 * 16 + u) * __ldg(w2 + 8832 + u * 96 + t2 * 6 + w);
            v = M.s21 * M.s1[3] * a;
        }
        // WORD-MAJOR layout: float index = ((combo*4 + g)*62 + slot)*4 + p
        g_C[((combo * 4 + g) * 62 + slot) * 4 + p] = v;
        return;
    }
    // ---- slot offset/pos table (1 block, threads 0..61) ----
    int s = threadIdx.x;
    if (s < 62) {
        int o0 = 0, o1 = 0, o2 = 0, o3 = 0, pp;
        if (s < 6)       { o0 = 0;  o1 = 12; o2 = 42;          pp = s; }
        else if (s < 9)  { int i = s - 6;  o0 = 13 + i; o1 = 43 + i;  pp = 8 + i * 8; }
        else if (s < 27) { int r = s - 9, i = r / 6, w = r - i * 6;
                           o0 = 1 + i; o1 = 9 + i; o2 = 21 + i; o3 = 34 + i; pp = 9 + i * 8 + w; }
        else if (s < 32) { int i = s - 27; o0 = 24 + i; o1 = 37 + i;  pp = 32 + i * 8; }
        else             { int r = s - 32, i = r / 6, w = r - i * 6;
                           o0 = 4 + i; o1 = 16 + i; o2 = 29 + i; o3 = 46 + i; pp = 33 + i * 8 + w; }
        g_tab[s] = (unsigned)(o0 | (o1 << 6) | (o2 << 12) | (o3 << 18) | (pp << 24));
    }
}

// ============================================================================
// K1: edge pass 1 — SH reds into node_sh[dst] + edge record (via packed PT)
// ============================================================================
__global__ void k_sh(const int* __restrict__ esrc, const int* __restrict__ edst, int E) {
    int e = blockIdx.x * blockDim.x + threadIdx.x;
    if (e >= E) return;
    int s = __ldg(esrc + e), d = __ldg(edst + e);
    float4 ps = __ldg(&g_PT[s]);
    float4 pd = __ldg(&g_PT[d]);
    float x = ps.x - pd.x, y = ps.y - pd.y, z = ps.z - pd.z;
    float sh[9];
    compute_sh(x, y, z, sh);
    float* np = reinterpret_cast<float*>(g_NS4) + (size_t)d * 12;
    red4(np + 0, sh[0], sh[1], sh[2], sh[3]);
    red4(np + 4, sh[4], sh[5], sh[6], sh[7]);
    atomicAdd(np + 8, sh[8]);
    int ms = __float_as_int(ps.w), md = __float_as_int(pd.w);
    int bits = (ms & 3) | ((md & 3) << 2) | ((md >> 2) << 4);   // zs | zd<<2 | g<<4
    g_ER[e] = make_float4(x, y, z, __int_as_float(bits));
}

// ============================================================================
// K2: per-edge TP1 geometry -> 13 vector reds into G[dst][z_src] (stride 52)
// ============================================================================
__global__ void k_tp1(const int* __restrict__ esrc, const int* __restrict__ edst,
                      int E, TP1P P) {
    int e = blockIdx.x * blockDim.x + threadIdx.x;
    if (e >= E) return;
    float4 er = g_ER[e];
    int s = __ldg(esrc + e), d = __ldg(edst + e);
    int zs = __float_as_int(er.w) & 3;
    float sh[9];
    compute_sh(er.x, er.y, er.z, sh);
    const float* ns = reinterpret_cast<const float*>(g_NS4) + (size_t)s * 12;
    float4 xa03 = *reinterpret_cast<const float4*>(ns);
    float4 xa47 = *reinterpret_cast<const float4*>(ns + 4);
    float xa[9] = {xa03.x, xa03.y, xa03.z, xa03.w, xa47.x, xa47.y, xa47.z, xa47.w, ns[8]};

    float g[51];
#pragma unroll
    for (int m = 0; m < 51; m++) g[m] = 0.f;

    float xa0 = xa[0];
    g[0] = xa0 * P.c000;
#pragma unroll
    for (int k = 0; k < 3; k++) g[1 + k] = xa0 * sh[1 + k] * P.d011[k];       // p1 (diag)
#pragma unroll
    for (int k = 0; k < 5; k++) g[4 + k] = xa0 * sh[4 + k] * P.d022[k];       // p2 (diag)
#pragma unroll
    for (int k = 0; k < 3; k++) g[9 + k] = xa[1 + k] * P.d101[k];             // p3 (diag)
    {
        float a = 0.f;
#pragma unroll
        for (int i = 0; i < 3; i++) a += xa[1 + i] * sh[1 + i] * P.d110[i];
        g[12] = a;                                                             // p4
    }
#pragma unroll
    for (int i = 0; i < 3; i++) {                      // p5->13 (c111), p6->16 (c112)
#pragma unroll
        for (int j = 0; j < 3; j++) {
            float f = xa[1 + i] * sh[1 + j];
#pragma unroll
            for (int k = 0; k < 3; k++) g[13 + k] += f * P.c111[(i * 3 + j) * 3 + k];
#pragma unroll
            for (int k = 0; k < 5; k++) g[16 + k] += f * P.c112[(i * 3 + j) * 5 + k];
        }
    }
#pragma unroll
    for (int i = 0; i < 3; i++) {                      // p7->21 (c121), p8->24 (c122)
#pragma unroll
        for (int j = 0; j < 5; j++) {
            float f = xa[1 + i] * sh[4 + j];
#pragma unroll
            for (int k = 0; k < 3; k++) g[21 + k] += f * P.c121[(i * 5 + j) * 3 + k];
#pragma unroll
            for (int k = 0; k < 5; k++) g[24 + k] += f * P.c122[(i * 5 + j) * 5 + k];
        }
    }
#pragma unroll
    for (int k = 0; k < 5; k++) g[29 + k] = xa[4 + k] * P.d202[k];            // p9 (diag)
#pragma unroll
    for (int i = 0; i < 5; i++) {                      // p10->34 (c211), p11->37 (c212)
#pragma unroll
        for (int j = 0; j < 3; j++) {
            float f = xa[4 + i] * sh[1 + j];
#pragma unroll
            for (int k = 0; k < 3; k++) g[34 + k] += f * P.c211[(i * 3 + j) * 3 + k];
#pragma unroll
            for (int k = 0; k < 5; k++) g[37 + k] += f * P.c212[(i * 3 + j) * 5 + k];
        }
    }
    {
        float a = 0.f;
#pragma unroll
        for (int i = 0; i < 5; i++) a += xa[4 + i] * sh[4 + i] * P.d220[i];
        g[42] = a;                                                             // p12
    }
#pragma unroll
    for (int i = 0; i < 5; i++) {                      // p13->43 (c221), p14->46 (c222)
#pragma unroll
        for (int j = 0; j < 5; j++) {
            float f = xa[4 + i] * sh[4 + j];
#pragma unroll
            for (int k = 0; k < 3; k++) g[43 + k] += f * P.c221[(i * 5 + j) * 3 + k];
#pragma unroll
            for (int k = 0; k < 5; k++) g[46 + k] += f * P.c222[(i * 5 + j) * 5 + k];
        }
    }

    float* Gp = reinterpret_cast<float*>(g_G4) + ((size_t)d * 4 + zs) * GR;
#pragma unroll
    for (int m = 0; m < 48; m += 4) red4(Gp + m, g[m], g[m + 1], g[m + 2], g[m + 3]);
    red4(Gp + 48, g[48], g[49], g[50], 0.f);           // index 51 is a pad
}

// ============================================================================
// K3: Q[n][zd][·] — WARP = (node, half). Each warp handles 31 slots (one
//     half), halving the per-warp serial chain and doubling independent
//     chains vs warp-per-node. Pad zeroing moved to the parallel staging
//     phase (was a divergent single-lane serial tail).
//     Block = 256 thr = 8 warps = 4 nodes x 2 halves. Re-zeroes consumed G/NS.
// ============================================================================
__global__ void __launch_bounds__(256) k_q() {
    __shared__ float sG[4 * 4 * GR];     // 4 nodes x 208 floats
    int tid = threadIdx.x;
    int warp = tid >> 5, lane = tid & 31;
    int local = warp >> 1, half = warp & 1;
    int n = blockIdx.x * 4 + local;

    const float4 z4 = make_float4(0.f, 0.f, 0.f, 0.f);
    {
        float4* dst = reinterpret_cast<float4*>(sG);
        size_t base = (size_t)blockIdx.x * 208;
        if (tid < 208) {
            dst[tid] = g_G4[base + tid];
            g_G4[base + tid] = z4;
        } else if (tid < 220) {
            g_NS4[(size_t)blockIdx.x * 12 + (tid - 208)] = z4;
        }
        // Q pad zeroing: 4 nodes x 4 zd x 10 pads = 160 stores
        if (tid < 160) {
            int nd = tid / 40, rr = tid - nd * 40, zd = rr / 10, pk = rr - zd * 10;
            int pp = (pk < 2) ? (6 + pk) : (15 + 8 * (pk - 2));
            reinterpret_cast<float*>(g_Q4)[((size_t)(blockIdx.x * 4 + nd) * 4 + zd) * QR + pp] = 0.f;
        }
    }
    __syncthreads();

    if (lane == 31) return;
    int s = lane + half * 31;                           // 0..30 or 31..61

    int zn = __float_as_int(__ldg(&g_PT[n]).w) & 3;
    const float4* C4g = reinterpret_cast<const float4*>(g_C);
    int combo_base = zn * 4;
    const float* Gn = &sG[local * 4 * GR];
    float* Qbase = reinterpret_cast<float*>(g_Q4) + (size_t)n * 4 * QR;

    unsigned tab = __ldg(&g_tab[s]);
    int o0 = tab & 63, o1 = (tab >> 6) & 63, o2 = (tab >> 12) & 63, o3 = (tab >> 18) & 63;
    int pos = tab >> 24;
    float gv[16];
#pragma unroll
    for (int g = 0; g < 4; g++) {
        gv[g * 4 + 0] = Gn[g * GR + o0];
        gv[g * 4 + 1] = Gn[g * GR + o1];
        gv[g * 4 + 2] = Gn[g * GR + o2];
        gv[g * 4 + 3] = Gn[g * GR + o3];
    }
#pragma unroll
    for (int zd = 0; zd < 4; zd++) {
        int combo = combo_base + zd;
        // word-major: instruction g reads lane-contiguous float4s
        float4 c0 = __ldg(C4g + (combo * 4 + 0) * 62 + s);
        float4 c1 = __ldg(C4g + (combo * 4 + 1) * 62 + s);
        float4 c2 = __ldg(C4g + (combo * 4 + 2) * 62 + s);
        float4 c3 = __ldg(C4g + (combo * 4 + 3) * 62 + s);
        float acc;
        acc  = c0.x * gv[0]  + c0.y * gv[1]  + c0.z * gv[2]  + c0.w * gv[3];
        acc += c1.x * gv[4]  + c1.y * gv[5]  + c1.z * gv[6]  + c1.w * gv[7];
        acc += c2.x * gv[8]  + c2.y * gv[9]  + c2.z * gv[10] + c2.w * gv[11];
        acc += c3.x * gv[12] + c3.y * gv[13] + c3.z * gv[14] + c3.w * gv[15];
        Qbase[zd * QR + pos] = acc;
    }
}

// ============================================================================
// K4: per-edge TP2 via Q — TWO edges per thread, loads interleaved for MLP.
// ============================================================================
__global__ void k_tp2(const int* __restrict__ esrc, int E, TP2P P) {
    int t = blockIdx.x * blockDim.x + threadIdx.x;
    int e0 = t << 1;
    if (e0 >= E) return;
    int e1 = e0 | 1;
    bool h1 = (e1 < E);
    int e1c = h1 ? e1 : e0;

    float4 erA = g_ER[e0];
    float4 erB = g_ER[e1c];
    int sA = __ldg(esrc + e0);
    int sB = __ldg(esrc + e1c);
    int bitsA = __float_as_int(erA.w);
    int bitsB = __float_as_int(erB.w);

    const float4* qA = &g_Q4[((size_t)sA * 4 + ((bitsA >> 2) & 3)) * (QR / 4)];
    const float4* qB = &g_Q4[((size_t)sB * 4 + ((bitsB >> 2) & 3)) * (QR / 4)];

    float4 haA0 = __ldg(qA), haA1 = __ldg(qA + 1);
    float4 haB0 = __ldg(qB), haB1 = __ldg(qB + 1);

    float shA[9], shB[9];
    compute_sh(erA.x, erA.y, erA.z, shA);
    compute_sh(erB.x, erB.y, erB.z, shB);
    float vA[8], vB[8];
#pragma unroll
    for (int i = 0; i < 3; i++) { vA[i] = shA[1 + i] * P.d110[i]; vB[i] = shB[1 + i] * P.d110[i]; }
#pragma unroll
    for (int i = 0; i < 5; i++) { vA[3 + i] = shA[4 + i] * P.d220[i]; vB[3 + i] = shB[4 + i] * P.d220[i]; }

    float c0A = 0.f, a0A = haA0.x, a1A = haA0.y, a2A = haA0.z, a3A = haA0.w, a4A = haA1.x, a5A = haA1.y;
    float c0B = 0.f, a0B = haB0.x, a1B = haB0.y, a2B = haB0.z, a3B = haB0.w, a4B = haB1.x, a5B = haB1.y;

#pragma unroll
    for (int i = 0; i < 8; i++) {
        float4 pa = __ldg(qA + 2 + 2 * i);
        float4 pb = __ldg(qA + 3 + 2 * i);
        float4 pc = __ldg(qB + 2 + 2 * i);
        float4 pd = __ldg(qB + 3 + 2 * i);
        float va = vA[i], vb = vB[i];
        c0A += va * pa.x;
        a0A += va * pa.y; a1A += va * pa.z; a2A += va * pa.w;
        a3A += va * pb.x; a4A += va * pb.y; a5A += va * pb.z;
        c0B += vb * pc.x;
        a0B += vb * pc.y; a1B += vb * pc.z; a2B += vb * pc.w;
        a3B += vb * pd.x; a4B += vb * pd.y; a5B += vb * pd.z;
    }

    {
        int g = bitsA >> 4;
        float* og = reinterpret_cast<float*>(g_out8) + (size_t)g * 8;
        red4(og + 0, c0A, a0A, a1A, a2A);
        red4(og + 4, a3A, a4A, a5A, 0.f);
    }
    if (h1) {
        int g = bitsB >> 4;
        float* og = reinterpret_cast<float*>(g_out8) + (size_t)g * 8;
        red4(og + 0, c0B, a0B, a1B, a2B);
        red4(og + 4, a3B, a4B, a5B, 0.f);
    }
}

// ============================================================================
// K5: copy padded accumulator -> out (5000 x 7); re-zero out8 for next replay
// ============================================================================
__global__ void k_final(float* __restrict__ out) {
    int i = blockIdx.x * blockDim.x + threadIdx.x;
    if (i >= NGR * 7) return;
    int g = i / 7, j = i - g * 7;
    float* o8 = reinterpret_cast<float*>(g_out8) + (size_t)g * 8;
    out[i] = o8[j];
    o8[j] = 0.f;
    if (j == 0) o8[7] = 0.f;
}

// ============================================================================
// Host: Wigner 3j (mirrors reference)
// ============================================================================
static double hfact(int n) { double r = 1.0; for (int i = 2; i <= n; i++) r *= (double)i; return r; }

static double hcg(int j1, int j2, int j3, int m1, int m2, int m3) {
    if (m1 + m2 != m3) return 0.0;
    double pre = sqrt((2.0 * j3 + 1.0) * hfact(j3 + j1 - j2) * hfact(j3 - j1 + j2) *
                      hfact(j1 + j2 - j3) / hfact(j1 + j2 + j3 + 1));
    pre *= sqrt(hfact(j3 + m3) * hfact(j3 - m3) * hfact(j1 - m1) * hfact(j1 + m1) *
                hfact(j2 - m2) * hfact(j2 + m2));
    int kmin = 0;
    if (j2 - j3 - m1 > kmin) kmin = j2 - j3 - m1;
    if (j1 - j3 + m2 > kmin) kmin = j1 - j3 + m2;
    int kmax = j1 + j2 - j3;
    if (j1 - m1 < kmax) kmax = j1 - m1;
    if (j2 + m2 < kmax) kmax = j2 + m2;
    double s = 0.0;
    for (int k = kmin; k <= kmax; k++) {
        double den = hfact(k) * hfact(j1 + j2 - j3 - k) * hfact(j1 - m1 - k) *
                     hfact(j2 + m2 - k) * hfact(j3 - j2 + m1 + k) * hfact(j3 - j1 - m2 + k);
        s += ((k & 1) ? -1.0 : 1.0) / den;
    }
    return pre * s;
}

static void humat(int l, double Ur[5][5], double Ui[5][5]) {
    for (int a = 0; a < 5; a++) for (int b = 0; b < 5; b++) { Ur[a][b] = 0.0; Ui[a][b] = 0.0; }
    double is2 = 1.0 / sqrt(2.0);
    for (int m = -l; m <= l; m++) {
        int r = m + l;
        if (m > 0) {
            Ur[r][l - m] = is2;
            Ur[r][l + m] = ((m & 1) ? -1.0 : 1.0) * is2;
        } else if (m == 0) {
            Ur[l][l] = 1.0;
        } else {
            Ui[r][l + m] = is2;
            Ui[r][l - m] = -(((-m) & 1) ? -1.0 : 1.0) * is2;
        }
    }
}

static void hw3j(int l1, int l2, int l3, float* out) {
    int n1 = 2 * l1 + 1, n2 = 2 * l2 + 1, n3 = 2 * l3 + 1;
    double C[5][5][5];
    memset(C, 0, sizeof(C));
    for (int m1 = -l1; m1 <= l1; m1++)
        for (int m2 = -l2; m2 <= l2; m2++) {
            int m3 = m1 + m2;
            if (m3 < -l3 || m3 > l3) continue;
            C[m1 + l1][m2 + l2][m3 + l3] = hcg(l1, l2, l3, m1, m2, m3);
        }
    double U1r[5][5], U1i[5][5], U2r[5][5], U2i[5][5], U3r[5][5], U3i[5][5];
    humat(l1, U1r, U1i); humat(l2, U2r, U2i); humat(l3, U3r, U3i);
    double Tre[5][5][5], Tim[5][5][5];
    double maxr = 0.0, maxi = 0.0;
    for (int a = 0; a < n1; a++)
        for (int b = 0; b < n2; b++)
            for (int c = 0; c < n3; c++) {
                double sr = 0.0, si = 0.0;
                for (int m = 0; m < n1; m++)
                    for (int n = 0; n < n2; n++)
                        for (int o = 0; o < n3; o++) {
                            double cv = C[m][n][o];
                            if (cv == 0.0) continue;
                            double ar = U1r[a][m], ai = U1i[a][m];
                            double br = U2r[b][n], bi = U2i[b][n];
                            double qr = ar * br - ai * bi, qi = ar * bi + ai * br;
                            double cr = U3r[c][o], ci = -U3i[c][o];
                            double rr = qr * cr - qi * ci, ri = qr * ci + qi * cr;
                            sr += rr * cv; si += ri * cv;
                        }
                Tre[a][b][c] = sr; Tim[a][b][c] = si;
                if (fabs(sr) > maxr) maxr = fabs(sr);
                if (fabs(si) > maxi) maxi = fabs(si);
            }
    bool useR = (maxr >= maxi);
    double nrm = 0.0;
    for (int a = 0; a < n1; a++)
        for (int b = 0; b < n2; b++)
            for (int c = 0; c < n3; c++) {
                double v = useR ? Tre[a][b][c] : Tim[a][b][c];
                nrm += v * v;
            }
    nrm = sqrt(nrm);
    for (int a = 0; a < n1; a++)
        for (int b = 0; b < n2; b++)
            for (int c = 0; c < n3; c++) {
                double v = useR ? Tre[a][b][c] : Tim[a][b][c];
                out[(a * n2 + b) * n3 + c] = (float)(v / nrm);
            }
}

// ============================================================================
// kernel_launch
// ============================================================================
extern "C" void kernel_launch(void* const* d_in, const int* in_sizes, int n_in,
                              void* d_out, int out_size) {
    const float* pos   = (const float*)d_in[0];
    const int*   zarr  = (const int*)  d_in[1];
    const int*   batch = (const int*)  d_in[2];
    const int*   esrc  = (const int*)  d_in[3];
    const int*   edst  = (const int*)  d_in[4];
    const float* w1    = (const float*)d_in[5];
    const float* w2    = (const float*)d_in[6];
    float*       out   = (float*)d_out;
    int E = in_sizes[3];

    // ---- host precompute (capture-time only) ----
    float c000, c011[9], c022[25], c101[9], c110[9], c202[25], c220[25];
    TP1P P;
    hw3j(0, 0, 0, &c000);
    hw3j(0, 1, 1, c011);  hw3j(0, 2, 2, c022);
    hw3j(1, 0, 1, c101);  hw3j(1, 1, 0, c110);
    hw3j(2, 0, 2, c202);  hw3j(2, 2, 0, c220);
    hw3j(1, 1, 1, P.c111); hw3j(1, 1, 2, P.c112);
    hw3j(1, 2, 1, P.c121); hw3j(1, 2, 2, P.c122);
    hw3j(2, 1, 1, P.c211); hw3j(2, 1, 2, P.c212);
    hw3j(2, 2, 1, P.c221); hw3j(2, 2, 2, P.c222);
    P.c000 = c000;
    for (int k = 0; k < 3; k++) { P.d011[k] = c011[k * 3 + k]; P.d101[k] = c101[k * 3 + k]; P.d110[k] = c110[k * 3 + k]; }
    for (int k = 0; k < 5; k++) { P.d022[k] = c022[k * 5 + k]; P.d202[k] = c202[k * 5 + k]; P.d220[k] = c220[k * 5 + k]; }

    PREPP M;
    {
        const double fan1[5] = {48.0, 32.0, 64.0, 64.0, 32.0};
        const int l3c[5] = {0, 1, 1, 2, 2};
        for (int c = 0; c < 5; c++)
            M.s1[c] = (float)(4.0 * sqrt(2.0 * l3c[c] + 1.0) / sqrt(fan1[c]) / 3.0);
        M.s20 = (float)(2.0 / (sqrt(3.0) * sqrt(640.0)));
        M.s21 = (float)(2.0 / (sqrt(3.0) * sqrt(1664.0)));
        M.q0s = c000 * M.s21;
    }

    TP2P P2;
    memcpy(P2.d110, P.d110, sizeof(P2.d110));
    memcpy(P2.d220, P.d220, sizeof(P2.d220));

    int EB = (E + 255) / 256;

    // ---- pipeline (6 launches; zero-invariant maintained in-kernel) ----
    k_pt<<<PTB + 65, 256>>>(pos, zarr, batch, w1, w2, M);
    k_sh<<<EB, 256>>>(esrc, edst, E);
    k_tp1<<<EB, 256>>>(esrc, edst, E, P);
    k_q<<<NN / 4, 256>>>();
    k_tp2<<<(E / 2 + 255) / 256, 256>>>(esrc, E, P2);
    k_final<<<(NGR * 7 + 255) / 256, 256>>>(out);
}

// round 16
// speedup vs baseline: 1.1012x; 1.1012x over previous
#include <cuda_runtime.h>
#include <cuda_bf16.h>
#include <math.h>
#include <string.h>

// ============================================================================
// Problem constants
// ============================================================================
#define NN    20000
#define NGR   5000
#define EMAX  320000
#define GR    52             // padded per-(node,zs) G row (51 used + 1 pad)
#define QR    72             // padded per-(node,zd) Q row
#define CSTR  992            // 62 slots x 16 padded coeffs per (zn,zd) combo
#define PTB   79             // ceil(NN/256) blocks for node-table build

// ============================================================================
// Device scratch (static — no allocation allowed).
// INVARIANT: g_G4, g_NS4, g_out8 are zero at kernel_launch entry (zero-init at
// load; k_q re-zeroes G/NS after consuming, k_final re-zeroes out8).
// ============================================================================
__device__ float4 g_G4[(size_t)NN * 4 * GR / 4];     // 16.6 MB G accumulators
__device__ float4 g_NS4[(size_t)NN * 12 / 4];        // padded node_sh (9 used)
__device__ float4 g_Q4[(size_t)NN * 4 * QR / 4];     // 23 MB Q tables
// fused W1*W2 operator, WORD-MAJOR: [combo][g-word][slot] of float4
// index of float4: (combo*4 + g)*62 + slot
__device__ __align__(16) float g_C[16 * CSTR];
__device__ float4 g_out8[(size_t)NGR * 2];           // padded output accumulator
__device__ float4 g_ER[EMAX];                        // per-edge record: ev + meta
__device__ float4 g_PT[NN];                          // packed node table: pos + (z|batch<<2)
__device__ unsigned int g_tab[62];                   // per-slot: 4x6b G-offsets + 6b pos

// ============================================================================
// Parameter structs
// ============================================================================
struct TP1P {
    float c000;
    float d011[3], d022[5], d101[3], d110[3], d202[5], d220[5];
    float c111[27], c112[45], c121[45], c122[75];
    float c211[45], c212[75], c221[75], c222[125];
};
struct TP2P  { float d110[3]; float d220[5]; };
struct PREPP { float s1[5]; float s20, s21, q0s; };

// ============================================================================
// Helpers
// ============================================================================
__device__ __forceinline__ void compute_sh(float x, float y, float z, float sh[9]) {
    const float s3  = 1.7320508075688772f;
    const float s15 = 3.8729833462074170f;
    const float s5  = 2.2360679774997896f;
    float r2 = x * x + y * y + z * z;
    sh[0] = 1.0f;
    sh[1] = s3 * y; sh[2] = s3 * z; sh[3] = s3 * x;
    sh[4] = s15 * x * y;
    sh[5] = s15 * y * z;
    sh[6] = 0.5f * s5 * (3.0f * z * z - r2);
    sh[7] = s15 * x * z;
    sh[8] = 0.5f * s15 * (x * x - y * y);
}

__device__ __forceinline__ void red4(float* p, float a, float b, float c, float d) {
    asm volatile("red.global.add.v4.f32 [%0], {%1,%2,%3,%4};"
                 :: "l"(p), "f"(a), "f"(b), "f"(c), "f"(d) : "memory");
}

// ============================================================================
// K0 (fused): node table (blocks 0..78) + operator prep (79..142) + slot table (143)
// ============================================================================
__global__ void k_pt(const float* __restrict__ pos, const int* __restrict__ zarr,
                     const int* __restrict__ batch,
                     const float* __restrict__ w1, const float* __restrict__ w2,
                     PREPP M) {
    int b = blockIdx.x;
    if (b < PTB) {
        int n = b * 256 + threadIdx.x;
        if (n < NN) {
            float4 v;
            v.x = __ldg(pos + 3 * n + 0);
            v.y = __ldg(pos + 3 * n + 1);
            v.z = __ldg(pos + 3 * n + 2);
            v.w = __int_as_float(__ldg(zarr + n) | (__ldg(batch + n) << 2));
            g_PT[n] = v;
        }
        return;
    }
    if (b < PTB + 64) {
        // ---- operator prep (64 blocks: 16 combos x 4 slices of 992 coeffs) ----
        int r = b - PTB;
        int combo = r >> 2, slice = r & 3;
        int zn = combo >> 2, zd = combo & 3;
        int t2 = 4 * zn + zd;
        int f = slice * 256 + threadIdx.x;
        if (f >= CSTR) return;
        int slot = f >> 4, q = f & 15;
        int g = q >> 2, p = q & 3;
        int t1 = 4 * g + zn;
        float v = 0.f;
        if (slot < 6) {                                 // Q0: 3 live paths
            if (p < 3) {
                int off = (p == 0) ? 0 : (p == 1 ? 2048 : 5248);
                float a = 0.f;
                for (int u = 0; u < 64; u++)
                    a += __ldg(w1 + off + t1 * 64 + u) * __ldg(w2 + u * 96 + t2 * 6 + slot);
                v = M.q0s * M.s1[0] * a;
            }
        } else if (slot < 9) {                          // A1: 2 live paths
            if (p < 2) {
                int off = p ? 6272 : 3072;
                float a = 0.f;
                for (int u = 0; u < 24; u++)
                    a += __ldg(w1 + off + t1 * 24 + u) * __ldg(w2 + 6144 + u * 16 + t2);
                v = M.s20 * M.s1[1] * a;
            }
        } else if (slot < 27) {                         // B1: 4 live paths
            int w = (slot - 9) % 6;
            const int offs[4] = {1024, 1664, 3712, 4608};
            float a = 0.f;
            for (int u = 0; u < 24; u++)
                a += __ldg(w1 + offs[p] + t1 * 24 + u) * __ldg(w2 + 6528 + u * 96 + t2 * 6 + w);
            v = M.s21 * M.s1[2] * a;
        } else if (slot < 32) {                         // A2: 2 live paths
            if (p < 2) {
                int off = p ? 4992 : 4096;
                float a = 0.f;
                for (int u = 0; u < 16; u++)
                    a += __ldg(w1 + off + t1 * 16 + u) * __ldg(w2 + 10368 + u * 16 + t2);
                v = M.s20 * M.s1[4] * a;
            }
        } else {                                        // B2: 4 live paths
            int w = (slot - 32) % 6;
            const int offs[4] = {1408, 3456, 4352, 6656};
            float a = 0.f;
            for (int u = 0; u < 16; u++)
                a += __ldg(w1 + offs[p] + t1 * 16 + u) * __ldg(w2 + 8832 + u * 96 + t2 * 6 + w);
            v = M.s21 * M.s1[3] * a;
        }
        // WORD-MAJOR layout: float index = ((combo*4 + g)*62 + slot)*4 + p
        g_C[((combo * 4 + g) * 62 + slot) * 4 + p] = v;
        return;
    }
    // ---- slot offset/pos table (1 block, threads 0..61) ----
    int s = threadIdx.x;
    if (s < 62) {
        int o0 = 0, o1 = 0, o2 = 0, o3 = 0, pp;
        if (s < 6)       { o0 = 0;  o1 = 12; o2 = 42;          pp = s; }
        else if (s < 9)  { int i = s - 6;  o0 = 13 + i; o1 = 43 + i;  pp = 8 + i * 8; }
        else if (s < 27) { int r = s - 9, i = r / 6, w = r - i * 6;
                           o0 = 1 + i; o1 = 9 + i; o2 = 21 + i; o3 = 34 + i; pp = 9 + i * 8 + w; }
        else if (s < 32) { int i = s - 27; o0 = 24 + i; o1 = 37 + i;  pp = 32 + i * 8; }
        else             { int r = s - 32, i = r / 6, w = r - i * 6;
                           o0 = 4 + i; o1 = 16 + i; o2 = 29 + i; o3 = 46 + i; pp = 33 + i * 8 + w; }
        g_tab[s] = (unsigned)(o0 | (o1 << 6) | (o2 << 12) | (o3 << 18) | (pp << 24));
    }
}

// ============================================================================
// K1: edge pass 1 — SH reds into node_sh[dst] + edge record (via packed PT)
// ============================================================================
__global__ void k_sh(const int* __restrict__ esrc, const int* __restrict__ edst, int E) {
    int e = blockIdx.x * blockDim.x + threadIdx.x;
    if (e >= E) return;
    int s = __ldg(esrc + e), d = __ldg(edst + e);
    float4 ps = __ldg(&g_PT[s]);
    float4 pd = __ldg(&g_PT[d]);
    float x = ps.x - pd.x, y = ps.y - pd.y, z = ps.z - pd.z;
    float sh[9];
    compute_sh(x, y, z, sh);
    float* np = reinterpret_cast<float*>(g_NS4) + (size_t)d * 12;
    red4(np + 0, sh[0], sh[1], sh[2], sh[3]);
    red4(np + 4, sh[4], sh[5], sh[6], sh[7]);
    atomicAdd(np + 8, sh[8]);
    int ms = __float_as_int(ps.w), md = __float_as_int(pd.w);
    int bits = (ms & 3) | ((md & 3) << 2) | ((md >> 2) << 4);   // zs | zd<<2 | g<<4
    g_ER[e] = make_float4(x, y, z, __int_as_float(bits));
}

// ============================================================================
// K2: per-edge TP1 geometry -> 13 vector reds into G[dst][z_src] (stride 52)
// ============================================================================
__global__ void k_tp1(const int* __restrict__ esrc, const int* __restrict__ edst,
                      int E, TP1P P) {
    int e = blockIdx.x * blockDim.x + threadIdx.x;
    if (e >= E) return;
    float4 er = g_ER[e];
    int s = __ldg(esrc + e), d = __ldg(edst + e);
    int zs = __float_as_int(er.w) & 3;
    float sh[9];
    compute_sh(er.x, er.y, er.z, sh);
    const float* ns = reinterpret_cast<const float*>(g_NS4) + (size_t)s * 12;
    float4 xa03 = *reinterpret_cast<const float4*>(ns);
    float4 xa47 = *reinterpret_cast<const float4*>(ns + 4);
    float xa[9] = {xa03.x, xa03.y, xa03.z, xa03.w, xa47.x, xa47.y, xa47.z, xa47.w, ns[8]};

    float g[51];
#pragma unroll
    for (int m = 0; m < 51; m++) g[m] = 0.f;

    float xa0 = xa[0];
    g[0] = xa0 * P.c000;
#pragma unroll
    for (int k = 0; k < 3; k++) g[1 + k] = xa0 * sh[1 + k] * P.d011[k];       // p1 (diag)
#pragma unroll
    for (int k = 0; k < 5; k++) g[4 + k] = xa0 * sh[4 + k] * P.d022[k];       // p2 (diag)
#pragma unroll
    for (int k = 0; k < 3; k++) g[9 + k] = xa[1 + k] * P.d101[k];             // p3 (diag)
    {
        float a = 0.f;
#pragma unroll
        for (int i = 0; i < 3; i++) a += xa[1 + i] * sh[1 + i] * P.d110[i];
        g[12] = a;                                                             // p4
    }
#pragma unroll
    for (int i = 0; i < 3; i++) {                      // p5->13 (c111), p6->16 (c112)
#pragma unroll
        for (int j = 0; j < 3; j++) {
            float f = xa[1 + i] * sh[1 + j];
#pragma unroll
            for (int k = 0; k < 3; k++) g[13 + k] += f * P.c111[(i * 3 + j) * 3 + k];
#pragma unroll
            for (int k = 0; k < 5; k++) g[16 + k] += f * P.c112[(i * 3 + j) * 5 + k];
        }
    }
#pragma unroll
    for (int i = 0; i < 3; i++) {                      // p7->21 (c121), p8->24 (c122)
#pragma unroll
        for (int j = 0; j < 5; j++) {
            float f = xa[1 + i] * sh[4 + j];
#pragma unroll
            for (int k = 0; k < 3; k++) g[21 + k] += f * P.c121[(i * 5 + j) * 3 + k];
#pragma unroll
            for (int k = 0; k < 5; k++) g[24 + k] += f * P.c122[(i * 5 + j) * 5 + k];
        }
    }
#pragma unroll
    for (int k = 0; k < 5; k++) g[29 + k] = xa[4 + k] * P.d202[k];            // p9 (diag)
#pragma unroll
    for (int i = 0; i < 5; i++) {                      // p10->34 (c211), p11->37 (c212)
#pragma unroll
        for (int j = 0; j < 3; j++) {
            float f = xa[4 + i] * sh[1 + j];
#pragma unroll
            for (int k = 0; k < 3; k++) g[34 + k] += f * P.c211[(i * 3 + j) * 3 + k];
#pragma unroll
            for (int k = 0; k < 5; k++) g[37 + k] += f * P.c212[(i * 3 + j) * 5 + k];
        }
    }
    {
        float a = 0.f;
#pragma unroll
        for (int i = 0; i < 5; i++) a += xa[4 + i] * sh[4 + i] * P.d220[i];
        g[42] = a;                                                             // p12
    }
#pragma unroll
    for (int i = 0; i < 5; i++) {                      // p13->43 (c221), p14->46 (c222)
#pragma unroll
        for (int j = 0; j < 5; j++) {
            float f = xa[4 + i] * sh[4 + j];
#pragma unroll
            for (int k = 0; k < 3; k++) g[43 + k] += f * P.c221[(i * 5 + j) * 3 + k];
#pragma unroll
            for (int k = 0; k < 5; k++) g[46 + k] += f * P.c222[(i * 5 + j) * 5 + k];
        }
    }

    float* Gp = reinterpret_cast<float*>(g_G4) + ((size_t)d * 4 + zs) * GR;
#pragma unroll
    for (int m = 0; m < 48; m += 4) red4(Gp + m, g[m], g[m + 1], g[m + 2], g[m + 3]);
    red4(Gp + 48, g[48], g[49], g[50], 0.f);           // index 51 is a pad
}

// ============================================================================
// K3: Q[n][zd][·] — warp per NODE (R14 structure, best so far). Each lane
//     gathers its slot's 16 G values once (zd-invariant), then 4 coefficient
//     dot products with TREE-FORM accumulation (dependent-FMA depth 16 -> ~5).
//     Pad zeroing moved into the parallel staging phase.
//     Block = 256 thr = 8 warps = 8 nodes. Re-zeroes consumed G/NS rows.
// ============================================================================
__global__ void __launch_bounds__(256) k_q() {
    __shared__ float sG[8 * 4 * GR];     // 8 nodes x 208 floats
    int tid = threadIdx.x;
    int warp = tid >> 5, lane = tid & 31;
    int n = blockIdx.x * 8 + warp;

    const float4 z4 = make_float4(0.f, 0.f, 0.f, 0.f);
    {
        float4* dst = reinterpret_cast<float4*>(sG);
        size_t base = (size_t)blockIdx.x * 416;
#pragma unroll
        for (int i = tid; i < 416; i += 256) {
            dst[i] = g_G4[base + i];
            g_G4[base + i] = z4;
        }
        if (tid < 24) g_NS4[(size_t)blockIdx.x * 24 + tid] = z4;
        // Q pad zeroing: 8 nodes x 4 zd x 10 pads = 320 stores (parallel)
        for (int i = tid; i < 320; i += 256) {
            int nd = i / 40, rr = i - nd * 40, zd = rr / 10, pk = rr - zd * 10;
            int pp = (pk < 2) ? (6 + pk) : (15 + 8 * (pk - 2));
            reinterpret_cast<float*>(g_Q4)[((size_t)(blockIdx.x * 8 + nd) * 4 + zd) * QR + pp] = 0.f;
        }
    }
    __syncthreads();

    if (lane == 31) return;

    int zn = __float_as_int(__ldg(&g_PT[n]).w) & 3;
    const float4* C4g = reinterpret_cast<const float4*>(g_C);
    int combo_base = zn * 4;
    const float* Gn = &sG[warp * 4 * GR];
    float* Qbase = reinterpret_cast<float*>(g_Q4) + (size_t)n * 4 * QR;

#pragma unroll
    for (int half = 0; half < 2; half++) {
        int s = lane + half * 31;                       // 0..30, 31..61
        unsigned tab = __ldg(&g_tab[s]);
        int o0 = tab & 63, o1 = (tab >> 6) & 63, o2 = (tab >> 12) & 63, o3 = (tab >> 18) & 63;
        int pos = tab >> 24;
        float gv[16];
#pragma unroll
        for (int g = 0; g < 4; g++) {
            gv[g * 4 + 0] = Gn[g * GR + o0];
            gv[g * 4 + 1] = Gn[g * GR + o1];
            gv[g * 4 + 2] = Gn[g * GR + o2];
            gv[g * 4 + 3] = Gn[g * GR + o3];
        }
#pragma unroll
        for (int zd = 0; zd < 4; zd++) {
            int combo = combo_base + zd;
            // word-major: instruction g reads lane-contiguous float4s
            float4 c0 = __ldg(C4g + (combo * 4 + 0) * 62 + s);
            float4 c1 = __ldg(C4g + (combo * 4 + 1) * 62 + s);
            float4 c2 = __ldg(C4g + (combo * 4 + 2) * 62 + s);
            float4 c3 = __ldg(C4g + (combo * 4 + 3) * 62 + s);
            // tree-form accumulation: dependent-chain depth ~5 instead of 16
            float t0 = (c0.x * gv[0]  + c0.y * gv[1])  + (c0.z * gv[2]  + c0.w * gv[3]);
            float t1 = (c1.x * gv[4]  + c1.y * gv[5])  + (c1.z * gv[6]  + c1.w * gv[7]);
            float t2 = (c2.x * gv[8]  + c2.y * gv[9])  + (c2.z * gv[10] + c2.w * gv[11]);
            float t3 = (c3.x * gv[12] + c3.y * gv[13]) + (c3.z * gv[14] + c3.w * gv[15]);
            Qbase[zd * QR + pos] = (t0 + t1) + (t2 + t3);
        }
    }
}

// ============================================================================
// K4: per-edge TP2 via Q — TWO edges per thread, loads interleaved for MLP.
// ============================================================================
__global__ void k_tp2(const int* __restrict__ esrc, int E, TP2P P) {
    int t = blockIdx.x * blockDim.x + threadIdx.x;
    int e0 = t << 1;
    if (e0 >= E) return;
    int e1 = e0 | 1;
    bool h1 = (e1 < E);
    int e1c = h1 ? e1 : e0;

    float4 erA = g_ER[e0];
    float4 erB = g_ER[e1c];
    int sA = __ldg(esrc + e0);
    int sB = __ldg(esrc + e1c);
    int bitsA = __float_as_int(erA.w);
    int bitsB = __float_as_int(erB.w);

    const float4* qA = &g_Q4[((size_t)sA * 4 + ((bitsA >> 2) & 3)) * (QR / 4)];
    const float4* qB = &g_Q4[((size_t)sB * 4 + ((bitsB >> 2) & 3)) * (QR / 4)];

    float4 haA0 = __ldg(qA), haA1 = __ldg(qA + 1);
    float4 haB0 = __ldg(qB), haB1 = __ldg(qB + 1);

    float shA[9], shB[9];
    compute_sh(erA.x, erA.y, erA.z, shA);
    compute_sh(erB.x, erB.y, erB.z, shB);
    float vA[8], vB[8];
#pragma unroll
    for (int i = 0; i < 3; i++) { vA[i] = shA[1 + i] * P.d110[i]; vB[i] = shB[1 + i] * P.d110[i]; }
#pragma unroll
    for (int i = 0; i < 5; i++) { vA[3 + i] = shA[4 + i] * P.d220[i]; vB[3 + i] = shB[4 + i] * P.d220[i]; }

    float c0A = 0.f, a0A = haA0.x, a1A = haA0.y, a2A = haA0.z, a3A = haA0.w, a4A = haA1.x, a5A = haA1.y;
    float c0B = 0.f, a0B = haB0.x, a1B = haB0.y, a2B = haB0.z, a3B = haB0.w, a4B = haB1.x, a5B = haB1.y;

#pragma unroll
    for (int i = 0; i < 8; i++) {
        float4 pa = __ldg(qA + 2 + 2 * i);
        float4 pb = __ldg(qA + 3 + 2 * i);
        float4 pc = __ldg(qB + 2 + 2 * i);
        float4 pd = __ldg(qB + 3 + 2 * i);
        float va = vA[i], vb = vB[i];
        c0A += va * pa.x;
        a0A += va * pa.y; a1A += va * pa.z; a2A += va * pa.w;
        a3A += va * pb.x; a4A += va * pb.y; a5A += va * pb.z;
        c0B += vb * pc.x;
        a0B += vb * pc.y; a1B += vb * pc.z; a2B += vb * pc.w;
        a3B += vb * pd.x; a4B += vb * pd.y; a5B += vb * pd.z;
    }

    {
        int g = bitsA >> 4;
        float* og = reinterpret_cast<float*>(g_out8) + (size_t)g * 8;
        red4(og + 0, c0A, a0A, a1A, a2A);
        red4(og + 4, a3A, a4A, a5A, 0.f);
    }
    if (h1) {
        int g = bitsB >> 4;
        float* og = reinterpret_cast<float*>(g_out8) + (size_t)g * 8;
        red4(og + 0, c0B, a0B, a1B, a2B);
        red4(og + 4, a3B, a4B, a5B, 0.f);
    }
}

// ============================================================================
// K5: copy padded accumulator -> out (5000 x 7); re-zero out8 for next replay
// ============================================================================
__global__ void k_final(float* __restrict__ out) {
    int i = blockIdx.x * blockDim.x + threadIdx.x;
    if (i >= NGR * 7) return;
    int g = i / 7, j = i - g * 7;
    float* o8 = reinterpret_cast<float*>(g_out8) + (size_t)g * 8;
    out[i] = o8[j];
    o8[j] = 0.f;
    if (j == 0) o8[7] = 0.f;
}

// ============================================================================
// Host: Wigner 3j (mirrors reference)
// ============================================================================
static double hfact(int n) { double r = 1.0; for (int i = 2; i <= n; i++) r *= (double)i; return r; }

static double hcg(int j1, int j2, int j3, int m1, int m2, int m3) {
    if (m1 + m2 != m3) return 0.0;
    double pre = sqrt((2.0 * j3 + 1.0) * hfact(j3 + j1 - j2) * hfact(j3 - j1 + j2) *
                      hfact(j1 + j2 - j3) / hfact(j1 + j2 + j3 + 1));
    pre *= sqrt(hfact(j3 + m3) * hfact(j3 - m3) * hfact(j1 - m1) * hfact(j1 + m1) *
                hfact(j2 - m2) * hfact(j2 + m2));
    int kmin = 0;
    if (j2 - j3 - m1 > kmin) kmin = j2 - j3 - m1;
    if (j1 - j3 + m2 > kmin) kmin = j1 - j3 + m2;
    int kmax = j1 + j2 - j3;
    if (j1 - m1 < kmax) kmax = j1 - m1;
    if (j2 + m2 < kmax) kmax = j2 + m2;
    double s = 0.0;
    for (int k = kmin; k <= kmax; k++) {
        double den = hfact(k) * hfact(j1 + j2 - j3 - k) * hfact(j1 - m1 - k) *
                     hfact(j2 + m2 - k) * hfact(j3 - j2 + m1 + k) * hfact(j3 - j1 - m2 + k);
        s += ((k & 1) ? -1.0 : 1.0) / den;
    }
    return pre * s;
}

static void humat(int l, double Ur[5][5], double Ui[5][5]) {
    for (int a = 0; a < 5; a++) for (int b = 0; b < 5; b++) { Ur[a][b] = 0.0; Ui[a][b] = 0.0; }
    double is2 = 1.0 / sqrt(2.0);
    for (int m = -l; m <= l; m++) {
        int r = m + l;
        if (m > 0) {
            Ur[r][l - m] = is2;
            Ur[r][l + m] = ((m & 1) ? -1.0 : 1.0) * is2;
        } else if (m == 0) {
            Ur[l][l] = 1.0;
        } else {
            Ui[r][l + m] = is2;
            Ui[r][l - m] = -(((-m) & 1) ? -1.0 : 1.0) * is2;
        }
    }
}

static void hw3j(int l1, int l2, int l3, float* out) {
    int n1 = 2 * l1 + 1, n2 = 2 * l2 + 1, n3 = 2 * l3 + 1;
    double C[5][5][5];
    memset(C, 0, sizeof(C));
    for (int m1 = -l1; m1 <= l1; m1++)
        for (int m2 = -l2; m2 <= l2; m2++) {
            int m3 = m1 + m2;
            if (m3 < -l3 || m3 > l3) continue;
            C[m1 + l1][m2 + l2][m3 + l3] = hcg(l1, l2, l3, m1, m2, m3);
        }
    double U1r[5][5], U1i[5][5], U2r[5][5], U2i[5][5], U3r[5][5], U3i[5][5];
    humat(l1, U1r, U1i); humat(l2, U2r, U2i); humat(l3, U3r, U3i);
    double Tre[5][5][5], Tim[5][5][5];
    double maxr = 0.0, maxi = 0.0;
    for (int a = 0; a < n1; a++)
        for (int b = 0; b < n2; b++)
            for (int c = 0; c < n3; c++) {
                double sr = 0.0, si = 0.0;
                for (int m = 0; m < n1; m++)
                    for (int n = 0; n < n2; n++)
                        for (int o = 0; o < n3; o++) {
                            double cv = C[m][n][o];
                            if (cv == 0.0) continue;
                            double ar = U1r[a][m], ai = U1i[a][m];
                            double br = U2r[b][n], bi = U2i[b][n];
                            double qr = ar * br - ai * bi, qi = ar * bi + ai * br;
                            double cr = U3r[c][o], ci = -U3i[c][o];
                            double rr = qr * cr - qi * ci, ri = qr * ci + qi * cr;
                            sr += rr * cv; si += ri * cv;
                        }
                Tre[a][b][c] = sr; Tim[a][b][c] = si;
                if (fabs(sr) > maxr) maxr = fabs(sr);
                if (fabs(si) > maxi) maxi = fabs(si);
            }
    bool useR = (maxr >= maxi);
    double nrm = 0.0;
    for (int a = 0; a < n1; a++)
        for (int b = 0; b < n2; b++)
            for (int c = 0; c < n3; c++) {
                double v = useR ? Tre[a][b][c] : Tim[a][b][c];
                nrm += v * v;
            }
    nrm = sqrt(nrm);
    for (int a = 0; a < n1; a++)
        for (int b = 0; b < n2; b++)
            for (int c = 0; c < n3; c++) {
                double v = useR ? Tre[a][b][c] : Tim[a][b][c];
                out[(a * n2 + b) * n3 + c] = (float)(v / nrm);
            }
}

// ============================================================================
// kernel_launch
// ============================================================================
extern "C" void kernel_launch(void* const* d_in, const int* in_sizes, int n_in,
                              void* d_out, int out_size) {
    const float* pos   = (const float*)d_in[0];
    const int*   zarr  = (const int*)  d_in[1];
    const int*   batch = (const int*)  d_in[2];
    const int*   esrc  = (const int*)  d_in[3];
    const int*   edst  = (const int*)  d_in[4];
    const float* w1    = (const float*)d_in[5];
    const float* w2    = (const float*)d_in[6];
    float*       out   = (float*)d_out;
    int E = in_sizes[3];

    // ---- host precompute (capture-time only) ----
    float c000, c011[9], c022[25], c101[9], c110[9], c202[25], c220[25];
    TP1P P;
    hw3j(0, 0, 0, &c000);
    hw3j(0, 1, 1, c011);  hw3j(0, 2, 2, c022);
    hw3j(1, 0, 1, c101);  hw3j(1, 1, 0, c110);
    hw3j(2, 0, 2, c202);  hw3j(2, 2, 0, c220);
    hw3j(1, 1, 1, P.c111); hw3j(1, 1, 2, P.c112);
    hw3j(1, 2, 1, P.c121); hw3j(1, 2, 2, P.c122);
    hw3j(2, 1, 1, P.c211); hw3j(2, 1, 2, P.c212);
    hw3j(2, 2, 1, P.c221); hw3j(2, 2, 2, P.c222);
    P.c000 = c000;
    for (int k = 0; k < 3; k++) { P.d011[k] = c011[k * 3 + k]; P.d101[k] = c101[k * 3 + k]; P.d110[k] = c110[k * 3 + k]; }
    for (int k = 0; k < 5; k++) { P.d022[k] = c022[k * 5 + k]; P.d202[k] = c202[k * 5 + k]; P.d220[k] = c220[k * 5 + k]; }

    PREPP M;
    {
        const double fan1[5] = {48.0, 32.0, 64.0, 64.0, 32.0};
        const int l3c[5] = {0, 1, 1, 2, 2};
        for (int c = 0; c < 5; c++)
            M.s1[c] = (float)(4.0 * sqrt(2.0 * l3c[c] + 1.0) / sqrt(fan1[c]) / 3.0);
        M.s20 = (float)(2.0 / (sqrt(3.0) * sqrt(640.0)));
        M.s21 = (float)(2.0 / (sqrt(3.0) * sqrt(1664.0)));
        M.q0s = c000 * M.s21;
    }

    TP2P P2;
    memcpy(P2.d110, P.d110, sizeof(P2.d110));
    memcpy(P2.d220, P.d220, sizeof(P2.d220));

    int EB = (E + 255) / 256;

    // ---- pipeline (6 launches; zero-invariant maintained in-kernel) ----
    k_pt<<<PTB + 65, 256>>>(pos, zarr, batch, w1, w2, M);
    k_sh<<<EB, 256>>>(esrc, edst, E);
    k_tp1<<<EB, 256>>>(esrc, edst, E, P);
    k_q<<<NN / 8, 256>>>();
    k_tp2<<<(E / 2 + 255) / 256, 256>>>(esrc, E, P2);
    k_final<<<(NGR * 7 + 255) / 256, 256>>>(out);
}